// round 2
// baseline (speedup 1.0000x reference)
#include <cuda_runtime.h>
#include <math.h>

#define S 4096
#define L 12
#define CE 64
#define CH 128
#define WE 256
#define HH 512
#define NTAGS 64
#define KC (CE + CH)   // 192
#define KW (CH + WE)   // 384
#define GW 128         // persistent word-LSTM grid (one wave, all resident)

// ---------------- scratch (device globals; no runtime allocation) ----------------
__device__ float g_Astep[S * KC];            //  3.0 MB  per-step char LSTM input [x, h]
__device__ float g_Bcat[4 * CH * KC];        //  0.4 MB  [Wih1 | Whh1]
__device__ float g_gates[S * 4 * CH];        //  8.0 MB  char gates
__device__ float g_Hc[S * CH];               //  2.0 MB
__device__ float g_Cc[S * CH];               //  2.0 MB
__device__ float g_win[S * KW];              //  6.0 MB  [char_rep | word vec]
__device__ float g_xw[(size_t)S * 4 * HH];   // 33.5 MB  word x-gates
__device__ float g_outs[(size_t)S * HH];     //  8.0 MB  word LSTM hidden outputs
__device__ float g_tag[S * NTAGS];           //  1.0 MB
__device__ float g_hbuf[2][HH];
__device__ unsigned g_bar;

__device__ __forceinline__ float sigf(float x) { return 1.f / (1.f + expf(-x)); }

// ---------------- generic fp32 GEMM: C[M,N] = A[M,K] * B[N,K]^T (+b1+b2) ----------
// Requirements: M%64==0, N%64==0, K%16==0. 256 threads, 64x64 tile, 4x4 microtile.
__global__ void sgemm_tn(int M, int N, int K,
                         const float* __restrict__ A,
                         const float* __restrict__ B,
                         const float* __restrict__ b1,
                         const float* __restrict__ b2,
                         float* __restrict__ C) {
    __shared__ float As[16][64];
    __shared__ float Bs[16][64];
    const int bn = blockIdx.x * 64, bm = blockIdx.y * 64;
    const int tid = threadIdx.x;
    const int tx = tid & 15, ty = tid >> 4;
    const int lr = tid >> 2, lk = (tid & 3) << 2;
    float acc[4][4] = {};
    for (int k0 = 0; k0 < K; k0 += 16) {
        float4 a4 = *(const float4*)(A + (size_t)(bm + lr) * K + k0 + lk);
        float4 b4 = *(const float4*)(B + (size_t)(bn + lr) * K + k0 + lk);
        As[lk + 0][lr] = a4.x; As[lk + 1][lr] = a4.y;
        As[lk + 2][lr] = a4.z; As[lk + 3][lr] = a4.w;
        Bs[lk + 0][lr] = b4.x; Bs[lk + 1][lr] = b4.y;
        Bs[lk + 2][lr] = b4.z; Bs[lk + 3][lr] = b4.w;
        __syncthreads();
#pragma unroll
        for (int k = 0; k < 16; k++) {
            float4 av = *(const float4*)(&As[k][ty << 2]);
            float4 bv = *(const float4*)(&Bs[k][tx << 2]);
            float a[4] = {av.x, av.y, av.z, av.w};
            float b[4] = {bv.x, bv.y, bv.z, bv.w};
#pragma unroll
            for (int i = 0; i < 4; i++)
#pragma unroll
                for (int j = 0; j < 4; j++) acc[i][j] += a[i] * b[j];
        }
        __syncthreads();
    }
#pragma unroll
    for (int i = 0; i < 4; i++) {
        int row = bm + (ty << 2) + i;
#pragma unroll
        for (int j = 0; j < 4; j++) {
            int col = bn + (tx << 2) + j;
            float v = acc[i][j];
            if (b1) v += b1[col];
            if (b2) v += b2[col];
            C[(size_t)row * N + col] = v;
        }
    }
}

// ---------------- small prep kernels ----------------
__global__ void k_bcat(const float* __restrict__ Wih1, const float* __restrict__ Whh1) {
    int i = blockIdx.x * 256 + threadIdx.x;
    if (i >= 4 * CH * KC) return;
    int n = i / KC, d = i % KC;
    g_Bcat[i] = (d < CE) ? Wih1[n * CE + d] : Whh1[n * CH + d - CE];
}

__global__ void k_init_char(const float* __restrict__ c_hx0, const float* __restrict__ c_cx0) {
    int i = blockIdx.x * 256 + threadIdx.x;
    if (i >= S * CH) return;
    int j = i & (CH - 1);
    g_Hc[i] = c_hx0[j];
    g_Cc[i] = c_cx0[j];
}

__global__ void k_astep(const int* __restrict__ c_seq, const float* __restrict__ char_emb, int l) {
    int i = blockIdx.x * 256 + threadIdx.x;
    if (i >= S * KC) return;
    int s = i / KC, d = i % KC;
    g_Astep[i] = (d < CE) ? char_emb[c_seq[s * L + l] * CE + d] : g_Hc[s * CH + d - CE];
}

__global__ void k_char_update() {
    int i = blockIdx.x * 256 + threadIdx.x;
    if (i >= S * CH) return;
    int s = i >> 7, j = i & 127;
    const float* g = g_gates + (size_t)s * 4 * CH;
    float gi = g[j], gf = g[CH + j], gg = g[2 * CH + j], go = g[3 * CH + j];
    float c = g_Cc[i];
    c = sigf(gf) * c + sigf(gi) * tanhf(gg);
    g_Cc[i] = c;
    g_Hc[i] = sigf(go) * tanhf(c);
}

__global__ void k_win(const int* __restrict__ w_seq, const float* __restrict__ word_emb) {
    int i = blockIdx.x * 256 + threadIdx.x;
    if (i >= S * KW) return;
    int s = i / KW, d = i % KW;
    g_win[i] = (d < CH) ? g_Hc[s * CH + d]
                        : word_emb[(size_t)w_seq[s] * WE + d - CH];
}

__global__ void k_init_word(const float* __restrict__ hx0) {
    int i = threadIdx.x;  // 512 threads
    g_hbuf[0][i] = hx0[i];
    g_hbuf[1][i] = 0.f;
    if (i == 0) g_bar = 0u;
}

// ---------------- persistent word-level LSTM (sequential recurrence) ----------------
// 128 CTAs x 256 threads; CTA blk owns hidden units [blk*4, blk*4+4) -> 16 gate rows.
// Whh2 slab held in registers (32 floats/thread). Grid barrier each step via
// threadfence + atomicAdd + ld.acquire spin (all CTAs co-resident: grid 128 <= 148 SMs).
__global__ void __launch_bounds__(256, 1) k_word(const float* __restrict__ Whh2,
                                                 const float* __restrict__ cx0) {
    __shared__ float hs[HH];
    __shared__ float rowsum[16];
    const int blk = blockIdx.x;
    const int tid = threadIdx.x;
    const int w = tid >> 5, lane = tid & 31;

    // preload weight slices into registers: warp w handles gate rows {2w, 2w+1};
    // row r = g*4+u maps to global Whh2 row g*512 + blk*4 + u.
    float4 w4[2][4];
#pragma unroll
    for (int rr = 0; rr < 2; rr++) {
        int r = w * 2 + rr;
        int grow = (r >> 2) * HH + blk * 4 + (r & 3);
#pragma unroll
        for (int c = 0; c < 4; c++)
            w4[rr][c] = *(const float4*)(Whh2 + (size_t)grow * HH + c * 128 + lane * 4);
    }
    float c_u = 0.f;
    if (tid < 4) c_u = cx0[blk * 4 + tid];

    for (int s = 0; s < S; s++) {
        const int p = s & 1;
        // prefetch this step's x-gates (independent of h)
        float xwv0 = 0.f, xwv1 = 0.f, xwv2 = 0.f, xwv3 = 0.f;
        if (tid < 4) {
            const float* xp = g_xw + (size_t)s * 2048 + blk * 4 + tid;
            xwv0 = xp[0]; xwv1 = xp[512]; xwv2 = xp[1024]; xwv3 = xp[1536];
        }
        // stage h into shared
        if (tid < 128)
            *(float4*)(&hs[tid * 4]) = *(const float4*)(&g_hbuf[p][tid * 4]);
        __syncthreads();

        float4 h4[4];
#pragma unroll
        for (int c = 0; c < 4; c++)
            h4[c] = *(const float4*)(&hs[c * 128 + lane * 4]);

#pragma unroll
        for (int rr = 0; rr < 2; rr++) {
            float acc = 0.f;
#pragma unroll
            for (int c = 0; c < 4; c++) {
                acc = fmaf(w4[rr][c].x, h4[c].x, acc);
                acc = fmaf(w4[rr][c].y, h4[c].y, acc);
                acc = fmaf(w4[rr][c].z, h4[c].z, acc);
                acc = fmaf(w4[rr][c].w, h4[c].w, acc);
            }
            acc += __shfl_xor_sync(0xffffffffu, acc, 16);
            acc += __shfl_xor_sync(0xffffffffu, acc, 8);
            acc += __shfl_xor_sync(0xffffffffu, acc, 4);
            acc += __shfl_xor_sync(0xffffffffu, acc, 2);
            acc += __shfl_xor_sync(0xffffffffu, acc, 1);
            if (lane == 0) rowsum[w * 2 + rr] = acc;
        }
        __syncthreads();

        if (tid < 4) {
            int u = tid;
            float gi = rowsum[u] + xwv0;
            float gf = rowsum[4 + u] + xwv1;
            float gg = rowsum[8 + u] + xwv2;
            float go = rowsum[12 + u] + xwv3;
            float c = sigf(gf) * c_u + sigf(gi) * tanhf(gg);
            c_u = c;
            float hv = sigf(go) * tanhf(c);
            g_hbuf[p ^ 1][blk * 4 + u] = hv;
            g_outs[(size_t)s * HH + blk * 4 + u] = hv;
        }
        __threadfence();
        __syncthreads();
        if (tid == 0) {
            atomicAdd(&g_bar, 1u);
            const unsigned target = (unsigned)(s + 1) * GW;
            unsigned v;
            do {
                asm volatile("ld.acquire.gpu.u32 %0, [%1];" : "=r"(v) : "l"(&g_bar) : "memory");
                if (v >= target) break;
                __nanosleep(32);
            } while (true);
        }
        __syncthreads();
    }
}

// ---------------- log-softmax over 64 tags, one warp per row ----------------
__global__ void k_logsoftmax(float* __restrict__ out) {
    int row = blockIdx.x * 4 + (threadIdx.x >> 5);
    int lane = threadIdx.x & 31;
    const float* t = g_tag + (size_t)row * NTAGS;
    float v0 = t[lane], v1 = t[lane + 32];
    float m = fmaxf(v0, v1);
#pragma unroll
    for (int o = 16; o; o >>= 1) m = fmaxf(m, __shfl_xor_sync(0xffffffffu, m, o));
    float e = expf(v0 - m) + expf(v1 - m);
#pragma unroll
    for (int o = 16; o; o >>= 1) e += __shfl_xor_sync(0xffffffffu, e, o);
    float lse = m + logf(e);
    out[(size_t)row * NTAGS + lane] = v0 - lse;
    out[(size_t)row * NTAGS + lane + 32] = v1 - lse;
}

// ---------------- launch ----------------
extern "C" void kernel_launch(void* const* d_in, const int* in_sizes, int n_in,
                              void* d_out, int out_size) {
    const int*   w_seq    = (const int*)d_in[0];
    const int*   c_seq    = (const int*)d_in[1];
    const float* char_emb = (const float*)d_in[2];
    const float* word_emb = (const float*)d_in[3];
    const float* c_hx0    = (const float*)d_in[4];
    const float* c_cx0    = (const float*)d_in[5];
    const float* hx0      = (const float*)d_in[6];
    const float* cx0      = (const float*)d_in[7];
    const float* Wih1     = (const float*)d_in[8];
    const float* Whh1     = (const float*)d_in[9];
    const float* bih1     = (const float*)d_in[10];
    const float* bhh1     = (const float*)d_in[11];
    const float* Wih2     = (const float*)d_in[12];
    const float* Whh2     = (const float*)d_in[13];
    const float* bih2     = (const float*)d_in[14];
    const float* bhh2     = (const float*)d_in[15];
    const float* W_out    = (const float*)d_in[16];
    const float* b_out    = (const float*)d_in[17];
    float* out = (float*)d_out;

    void *pA, *pB, *pG, *pW, *pX, *pO, *pT;
    cudaGetSymbolAddress(&pA, g_Astep);
    cudaGetSymbolAddress(&pB, g_Bcat);
    cudaGetSymbolAddress(&pG, g_gates);
    cudaGetSymbolAddress(&pW, g_win);
    cudaGetSymbolAddress(&pX, g_xw);
    cudaGetSymbolAddress(&pO, g_outs);
    cudaGetSymbolAddress(&pT, g_tag);

    k_bcat<<<(4 * CH * KC + 255) / 256, 256>>>(Wih1, Whh1);
    k_init_char<<<(S * CH + 255) / 256, 256>>>(c_hx0, c_cx0);

    // char LSTM: 12 fused-input steps (gather [x,h] -> GEMM -> pointwise update)
    for (int l = 0; l < L; l++) {
        k_astep<<<(S * KC + 255) / 256, 256>>>(c_seq, char_emb, l);
        sgemm_tn<<<dim3(4 * CH / 64, S / 64), 256>>>(S, 4 * CH, KC,
            (const float*)pA, (const float*)pB, bih1, bhh1, (float*)pG);
        k_char_update<<<(S * CH + 255) / 256, 256>>>();
    }

    // word sequence inputs and x-gates
    k_win<<<(S * KW + 255) / 256, 256>>>(w_seq, word_emb);
    sgemm_tn<<<dim3(4 * HH / 64, S / 64), 256>>>(S, 4 * HH, KW,
        (const float*)pW, Wih2, bih2, bhh2, (float*)pX);

    // sequential word LSTM (persistent, grid-barriered)
    k_init_word<<<1, 512>>>(hx0);
    k_word<<<GW, 256>>>(Whh2, cx0);

    // tags + log-softmax
    sgemm_tn<<<dim3(NTAGS / 64, S / 64), 256>>>(S, NTAGS, HH,
        (const float*)pO, W_out, b_out, nullptr, (float*)pT);
    k_logsoftmax<<<S / 4, 128>>>(out);
}

// round 3
// speedup vs baseline: 1.7179x; 1.7179x over previous
#include <cuda_runtime.h>
#include <math.h>

#define S 4096
#define L 12
#define CE 64
#define CH 128
#define WE 256
#define HH 512
#define NTAGS 64
#define KC (CE + CH)   // 192
#define KW (CH + WE)   // 384
#define GW 128         // persistent word-LSTM grid (one wave, all resident)

// ---------------- scratch (device globals; no runtime allocation) ----------------
__device__ float g_Bcat[4 * CH * KC];        //  0.4 MB  [Wih1 | Whh1]
__device__ float g_gates[S * 4 * CH];        //  8.0 MB  char gates
__device__ float g_Hc[S * CH];               //  2.0 MB
__device__ float g_Cc[S * CH];               //  2.0 MB
__device__ float g_xw[(size_t)S * 4 * HH];   // 33.5 MB  word x-gates
__device__ float g_outs[(size_t)S * HH];     //  8.0 MB  word LSTM hidden outputs
__device__ float g_tag[S * NTAGS];           //  1.0 MB
// tagged h exchange: pair = {float bits, step tag}; 2 buffers x 512 pairs, 16B-aligned
__device__ uint4 g_hpair[2][HH / 2];

__device__ __forceinline__ float sigf(float x) { return 1.f / (1.f + expf(-x)); }
__device__ __forceinline__ float tanha(float x) {
    float y; asm("tanh.approx.f32 %0, %1;" : "=f"(y) : "f"(x)); return y;
}
__device__ __forceinline__ float siga(float x) { return fmaf(tanha(0.5f * x), 0.5f, 0.5f); }

__device__ __forceinline__ uint4 ldv16(const uint4* p) {
    uint4 v;
    asm volatile("ld.volatile.global.v4.u32 {%0,%1,%2,%3}, [%4];"
                 : "=r"(v.x), "=r"(v.y), "=r"(v.z), "=r"(v.w) : "l"(p));
    return v;
}
__device__ __forceinline__ void stcg8(uint2* p, unsigned a, unsigned b) {
    asm volatile("st.global.cg.v2.u32 [%0], {%1,%2};" :: "l"(p), "r"(a), "r"(b) : "memory");
}

// ---------------- fp32 GEMM: C[M,N] = A[M,K] * B[N,K]^T (+b1+b2) ------------------
// mode 0: A plain. mode 1: A row s = [char_emb[idx[s*L+l]] | g_Hc[s]] (CE|CH).
// mode 2: A row s = [g_Hc[s] | emb[idx[s]]] (CH|WE).
// Requirements: M%64==0, N%64==0, K%16==0. 256 threads, 64x64 tile, 4x4 microtile.
__global__ void sgemm_tn(int M, int N, int K,
                         const float* __restrict__ A,
                         const float* __restrict__ B,
                         const float* __restrict__ b1,
                         const float* __restrict__ b2,
                         float* __restrict__ C,
                         int mode, const int* __restrict__ idx,
                         const float* __restrict__ emb, int l) {
    __shared__ float As[16][64];
    __shared__ float Bs[16][64];
    const int bn = blockIdx.x * 64, bm = blockIdx.y * 64;
    const int tid = threadIdx.x;
    const int tx = tid & 15, ty = tid >> 4;
    const int lr = tid >> 2, lk = (tid & 3) << 2;

    const int s = bm + lr;
    const float* rA0;
    const float* rA1 = nullptr;
    int split = 1 << 30;
    if (mode == 0) {
        rA0 = A + (size_t)s * K;
    } else if (mode == 1) {
        rA0 = emb + (size_t)idx[s * L + l] * CE;
        rA1 = g_Hc + (size_t)s * CH - CE;
        split = CE;
    } else {
        rA0 = g_Hc + (size_t)s * CH;
        rA1 = emb + (size_t)idx[s] * WE - CH;
        split = CH;
    }
    const float* rB = B + (size_t)(bn + lr) * K;

    float acc[4][4] = {};
    for (int k0 = 0; k0 < K; k0 += 16) {
        int d = k0 + lk;
        float4 a4 = (d < split) ? *(const float4*)(rA0 + d) : *(const float4*)(rA1 + d);
        float4 b4 = *(const float4*)(rB + d);
        As[lk + 0][lr] = a4.x; As[lk + 1][lr] = a4.y;
        As[lk + 2][lr] = a4.z; As[lk + 3][lr] = a4.w;
        Bs[lk + 0][lr] = b4.x; Bs[lk + 1][lr] = b4.y;
        Bs[lk + 2][lr] = b4.z; Bs[lk + 3][lr] = b4.w;
        __syncthreads();
#pragma unroll
        for (int k = 0; k < 16; k++) {
            float4 av = *(const float4*)(&As[k][ty << 2]);
            float4 bv = *(const float4*)(&Bs[k][tx << 2]);
            float a[4] = {av.x, av.y, av.z, av.w};
            float b[4] = {bv.x, bv.y, bv.z, bv.w};
#pragma unroll
            for (int i = 0; i < 4; i++)
#pragma unroll
                for (int j = 0; j < 4; j++) acc[i][j] += a[i] * b[j];
        }
        __syncthreads();
    }
#pragma unroll
    for (int i = 0; i < 4; i++) {
        int row = bm + (ty << 2) + i;
#pragma unroll
        for (int j = 0; j < 4; j++) {
            int col = bn + (tx << 2) + j;
            float v = acc[i][j];
            if (b1) v += b1[col];
            if (b2) v += b2[col];
            C[(size_t)row * N + col] = v;
        }
    }
}

// ---------------- small prep kernels ----------------
__global__ void k_bcat(const float* __restrict__ Wih1, const float* __restrict__ Whh1) {
    int i = blockIdx.x * 256 + threadIdx.x;
    if (i >= 4 * CH * KC) return;
    int n = i / KC, d = i % KC;
    g_Bcat[i] = (d < CE) ? Wih1[n * CE + d] : Whh1[n * CH + d - CE];
}

__global__ void k_init_char(const float* __restrict__ c_hx0, const float* __restrict__ c_cx0) {
    int i = blockIdx.x * 256 + threadIdx.x;
    if (i >= S * CH) return;
    int j = i & (CH - 1);
    g_Hc[i] = c_hx0[j];
    g_Cc[i] = c_cx0[j];
}

__global__ void k_char_update() {
    int i = blockIdx.x * 256 + threadIdx.x;
    if (i >= S * CH) return;
    int s = i >> 7, j = i & 127;
    const float* g = g_gates + (size_t)s * 4 * CH;
    float gi = g[j], gf = g[CH + j], gg = g[2 * CH + j], go = g[3 * CH + j];
    float c = g_Cc[i];
    c = sigf(gf) * c + sigf(gi) * tanhf(gg);
    g_Cc[i] = c;
    g_Hc[i] = sigf(go) * tanhf(c);
}

__global__ void k_init_word(const float* __restrict__ hx0) {
    int i = threadIdx.x;  // 512 threads
    ((uint2*)g_hpair[0])[i] = make_uint2(__float_as_uint(hx0[i]), 0u);
    ((uint2*)g_hpair[1])[i] = make_uint2(0u, 0x80000000u);
}

// ---------------- persistent word-level LSTM (sequential recurrence) ----------------
// 128 CTAs x 256 threads; CTA blk owns hidden units [blk*4, blk*4+4) -> 16 gate rows.
// Whh2 slab in registers. Synchronization is implicit: each h value is published as a
// tagged 8B word {h_bits, step+1}; readers spin (ld.volatile) until tag == step.
// Tag protocol also prevents buffer overwrite races (see derivation in analysis).
__global__ void __launch_bounds__(256, 1) k_word(const float* __restrict__ Whh2,
                                                 const float* __restrict__ cx0) {
    __shared__ float hs[HH];
    __shared__ float rowsum[16];
    const int blk = blockIdx.x;
    const int tid = threadIdx.x;
    const int w = tid >> 5, lane = tid & 31;

    // weight slices: warp w owns gate rows {2w, 2w+1}; row r -> Whh2 row (r>>2)*HH + blk*4 + (r&3)
    float4 w4[2][4];
#pragma unroll
    for (int rr = 0; rr < 2; rr++) {
        int r = w * 2 + rr;
        int grow = (r >> 2) * HH + blk * 4 + (r & 3);
#pragma unroll
        for (int c = 0; c < 4; c++)
            w4[rr][c] = *(const float4*)(Whh2 + (size_t)grow * HH + c * 128 + lane * 4);
    }
    float c_u = 0.f;
    if (w == 0 && lane < 4) c_u = cx0[blk * 4 + lane];

    // x-gate prefetch (one step ahead): lane r<16 of warp0 holds xw row (r>>2)*512+blk*4+(r&3)
    const size_t xoff = (size_t)((lane >> 2) * HH + blk * 4 + (lane & 3));
    float xw_cur = 0.f;
    if (w == 0 && lane < 16) xw_cur = __ldg(g_xw + xoff);

    for (int s = 0; s < S; s++) {
        // prefetch next step's x-gates (overlaps with the poll below)
        float xw_nxt = 0.f;
        if (w == 0 && lane < 16) {
            int sn = (s + 1 < S) ? s + 1 : s;
            xw_nxt = __ldg(g_xw + (size_t)sn * 2048 + xoff);
        }
        // poll tagged h[s]: each thread owns 2 pairs (16B)
        const uint4* src = &g_hpair[s & 1][tid];
        const unsigned tg = (unsigned)s;
        uint4 v;
        do { v = ldv16(src); } while (v.y != tg || v.w != tg);
        hs[2 * tid]     = __uint_as_float(v.x);
        hs[2 * tid + 1] = __uint_as_float(v.z);
        __syncthreads();

        float4 h4[4];
#pragma unroll
        for (int c = 0; c < 4; c++)
            h4[c] = *(const float4*)(&hs[c * 128 + lane * 4]);

#pragma unroll
        for (int rr = 0; rr < 2; rr++) {
            float acc = 0.f;
#pragma unroll
            for (int c = 0; c < 4; c++) {
                acc = fmaf(w4[rr][c].x, h4[c].x, acc);
                acc = fmaf(w4[rr][c].y, h4[c].y, acc);
                acc = fmaf(w4[rr][c].z, h4[c].z, acc);
                acc = fmaf(w4[rr][c].w, h4[c].w, acc);
            }
            acc += __shfl_xor_sync(0xffffffffu, acc, 16);
            acc += __shfl_xor_sync(0xffffffffu, acc, 8);
            acc += __shfl_xor_sync(0xffffffffu, acc, 4);
            acc += __shfl_xor_sync(0xffffffffu, acc, 2);
            acc += __shfl_xor_sync(0xffffffffu, acc, 1);
            if (lane == 0) rowsum[w * 2 + rr] = acc;
        }
        __syncthreads();

        if (w == 0) {
            // activations in 16 lanes: rows 0-7 (i,f) and 12-15 (o) sigmoid, 8-11 (g) tanh
            float r = (lane < 16) ? rowsum[lane] + xw_cur : 0.f;
            float act = (lane < 8 || lane >= 12) ? siga(r) : tanha(r);
            float ai = __shfl_sync(0xffffffffu, act, lane & 3);
            float af = __shfl_sync(0xffffffffu, act, 4 + (lane & 3));
            float ag = __shfl_sync(0xffffffffu, act, 8 + (lane & 3));
            float ao = __shfl_sync(0xffffffffu, act, 12 + (lane & 3));
            if (lane < 4) {
                c_u = fmaf(af, c_u, ai * ag);
                float hv = ao * tanha(c_u);
                stcg8(((uint2*)g_hpair[(s + 1) & 1]) + blk * 4 + lane,
                      __float_as_uint(hv), (unsigned)(s + 1));
                g_outs[(size_t)s * HH + blk * 4 + lane] = hv;
            }
            xw_cur = xw_nxt;
        }
    }
}

// ---------------- log-softmax over 64 tags, one warp per row ----------------
__global__ void k_logsoftmax(float* __restrict__ out) {
    int row = blockIdx.x * 4 + (threadIdx.x >> 5);
    int lane = threadIdx.x & 31;
    const float* t = g_tag + (size_t)row * NTAGS;
    float v0 = t[lane], v1 = t[lane + 32];
    float m = fmaxf(v0, v1);
#pragma unroll
    for (int o = 16; o; o >>= 1) m = fmaxf(m, __shfl_xor_sync(0xffffffffu, m, o));
    float e = expf(v0 - m) + expf(v1 - m);
#pragma unroll
    for (int o = 16; o; o >>= 1) e += __shfl_xor_sync(0xffffffffu, e, o);
    float lse = m + logf(e);
    out[(size_t)row * NTAGS + lane] = v0 - lse;
    out[(size_t)row * NTAGS + lane + 32] = v1 - lse;
}

// ---------------- launch ----------------
extern "C" void kernel_launch(void* const* d_in, const int* in_sizes, int n_in,
                              void* d_out, int out_size) {
    const int*   w_seq    = (const int*)d_in[0];
    const int*   c_seq    = (const int*)d_in[1];
    const float* char_emb = (const float*)d_in[2];
    const float* word_emb = (const float*)d_in[3];
    const float* c_hx0    = (const float*)d_in[4];
    const float* c_cx0    = (const float*)d_in[5];
    const float* hx0      = (const float*)d_in[6];
    const float* cx0      = (const float*)d_in[7];
    const float* Wih1     = (const float*)d_in[8];
    const float* Whh1     = (const float*)d_in[9];
    const float* bih1     = (const float*)d_in[10];
    const float* bhh1     = (const float*)d_in[11];
    const float* Wih2     = (const float*)d_in[12];
    const float* Whh2     = (const float*)d_in[13];
    const float* bih2     = (const float*)d_in[14];
    const float* bhh2     = (const float*)d_in[15];
    const float* W_out    = (const float*)d_in[16];
    const float* b_out    = (const float*)d_in[17];
    float* out = (float*)d_out;

    void *pB, *pG, *pX, *pO, *pT;
    cudaGetSymbolAddress(&pB, g_Bcat);
    cudaGetSymbolAddress(&pG, g_gates);
    cudaGetSymbolAddress(&pX, g_xw);
    cudaGetSymbolAddress(&pO, g_outs);
    cudaGetSymbolAddress(&pT, g_tag);

    k_bcat<<<(4 * CH * KC + 255) / 256, 256>>>(Wih1, Whh1);
    k_init_char<<<(S * CH + 255) / 256, 256>>>(c_hx0, c_cx0);

    // char LSTM: 12 steps, A gathered in-GEMM (mode 1)
    for (int l = 0; l < L; l++) {
        sgemm_tn<<<dim3(4 * CH / 64, S / 64), 256>>>(S, 4 * CH, KC,
            nullptr, (const float*)pB, bih1, bhh1, (float*)pG, 1, c_seq, char_emb, l);
        k_char_update<<<(S * CH + 255) / 256, 256>>>();
    }

    // word x-gates, A gathered in-GEMM (mode 2)
    sgemm_tn<<<dim3(4 * HH / 64, S / 64), 256>>>(S, 4 * HH, KW,
        nullptr, Wih2, bih2, bhh2, (float*)pX, 2, w_seq, word_emb, 0);

    // sequential word LSTM (persistent, tag-synchronized)
    k_init_word<<<1, 512>>>(hx0);
    k_word<<<GW, 256>>>(Whh2, cx0);

    // tags + log-softmax
    sgemm_tn<<<dim3(NTAGS / 64, S / 64), 256>>>(S, NTAGS, HH,
        (const float*)pO, W_out, b_out, nullptr, (float*)pT, 0, nullptr, nullptr, 0);
    k_logsoftmax<<<S / 4, 128>>>(out);
}